// round 14
// baseline (speedup 1.0000x reference)
#include <cuda_runtime.h>

#define NN    8192
#define DD    64
#define HH    4096
#define SS    2          // samples per block
#define NP    8          // hidden-unit pairs per thread (16 units)
#define BLOCK 512

typedef unsigned long long u64;

static __device__ __forceinline__ u64 pk(float lo, float hi) {
    u64 r; asm("mov.b64 %0,{%1,%2};" : "=l"(r) : "f"(lo), "f"(hi)); return r;
}
static __device__ __forceinline__ void upk(float& lo, float& hi, u64 v) {
    asm("mov.b64 {%0,%1},%2;" : "=f"(lo), "=f"(hi) : "l"(v));
}
static __device__ __forceinline__ u64 fma2(u64 a, u64 b, u64 c) {
    u64 d; asm("fma.rn.f32x2 %0,%1,%2,%3;" : "=l"(d) : "l"(a), "l"(b), "l"(c)); return d;
}
static __device__ __forceinline__ u64 mul2(u64 a, u64 b) {
    u64 d; asm("mul.rn.f32x2 %0,%1,%2;" : "=l"(d) : "l"(a), "l"(b)); return d;
}
static __device__ __forceinline__ u64 add2(u64 a, u64 b) {
    u64 d; asm("add.rn.f32x2 %0,%1,%2;" : "=l"(d) : "l"(a), "l"(b)); return d;
}
static __device__ __forceinline__ float frsq(float x) {
    float r; asm("rsqrt.approx.f32 %0,%1;" : "=f"(r) : "f"(x)); return r;
}
static __device__ __forceinline__ float ftanh(float x) {
    float e = __expf(2.0f * x);
    return 1.0f - __fdividef(2.0f, e + 1.0f);
}
// MUFU.TANH path: 1 MUFU per element, zero FMA (sm_75+)
static __device__ __forceinline__ u64 tanh2_approx(u64 hA) {
    float h0, h1; upk(h0, h1, hA);
    float t0, t1;
    asm("tanh.approx.f32 %0,%1;" : "=f"(t0) : "f"(h0));
    asm("tanh.approx.f32 %0,%1;" : "=f"(t1) : "f"(h1));
    return pk(t0, t1);
}
// FMA-path packed tanh: t = s*rsqrt(1+s^2), s = h*P(h^2) (deg-3 sinh Taylor)
static __device__ __forceinline__ u64 tanh2_fma(u64 hA) {
    const u64 C3  = pk(1.98412698e-4f, 1.98412698e-4f);   // 1/7!
    const u64 C2  = pk(8.33333333e-3f, 8.33333333e-3f);   // 1/5!
    const u64 C1  = pk(1.66666667e-1f, 1.66666667e-1f);   // 1/3!
    const u64 ONE = pk(1.0f, 1.0f);
    u64 y = mul2(hA, hA);
    u64 p = fma2(C3, y, C2);
    p = fma2(p, y, C1);
    p = fma2(p, y, ONE);
    u64 sv = mul2(p, hA);
    u64 dd2 = fma2(sv, sv, ONE);
    float dl, dh; upk(dl, dh, dd2);
    return mul2(sv, pk(frsq(dl), frsq(dh)));
}

// smem: packed W2 + packed spins + partials + products (W1 in L1 via LDG)
#define SW2_U 1024                       // ulonglong2 entries per m-plane
#define NPW   32                         // partials per (step, sample)
#define SMEM_BYTES (2*SW2_U*16 + SS*DD*8 + DD*SS*NPW*8 + SS*2*4)

__global__ void __launch_bounds__(BLOCK, 2)
qnade_kernel(const float* __restrict__ gx,  const float* __restrict__ gW1,
             const float* __restrict__ gb1, const float* __restrict__ gW2,
             const float* __restrict__ gb2, float* __restrict__ gout)
{
    extern __shared__ char sm_[];
    ulonglong2* sW2   = (ulonglong2*)sm_;                   // [2][1024] (m-major)
    u64*        sXp   = (u64*)(sW2 + 2 * SW2_U);            // [SS][DD] packed spins
    float2*     sPart = (float2*)(sXp + SS * DD);           // [DD][SS][NPW]
    float*      sProd = (float*)(sPart + DD * SS * NPW);    // [SS][2]

    const int tid  = threadIdx.x;
    const int s    = tid >> 8;       // sample within block (0..1)
    const int wg   = tid & 255;      // thread within sample group
    const int wis  = wg >> 5;        // warp within sample group (0..7)
    const int lane = tid & 31;
    const int n    = blockIdx.x * SS + s;

    for (int i = tid; i < SS * DD; i += BLOCK) {
        float xv = gx[blockIdx.x * SS * DD + i];
        sXp[i] = pk(xv, xv);
    }

    // stage W2 pre-transposed: float4 p = 2*f4+m -> plane m, entry f4:
    // {pk(w0_even,w0_odd), pk(w1_even,w1_odd)} for unit pair 2p,2p+1
    {
        const float4* w2v = (const float4*)gW2;             // [H,2] -> 2048 float4
        for (int p = tid; p < 2 * SW2_U; p += BLOCK) {
            float4 w = w2v[p];
            ulonglong2 e;
            e.x = pk(w.x, w.z);
            e.y = pk(w.y, w.w);
            sW2[((p & 1) << 10) + (p >> 1)] = e;
        }
    }

    // persistent packed state: thread wg owns units 4*f4..4*f4+3, f4 = wg+256*k4
    u64 hp[NP];
    {
        const ulonglong2* b1v = (const ulonglong2*)gb1;
#pragma unroll
        for (int k4 = 0; k4 < NP / 2; k4++) {
            ulonglong2 b = b1v[wg + 256 * k4];
            hp[2*k4+0] = b.x; hp[2*k4+1] = b.y;
        }
    }
    __syncthreads();   // sW2 / sXp staged

    for (int ds = 0; ds < DD; ds += 2) {
        if ((ds & 15) == 0) __syncthreads();  // light drift control for L1
        const u64 x0p = sXp[s * DD + ds];
        const u64 x1p = sXp[s * DD + ds + 1];
        const ulonglong2* w1a = (const ulonglong2*)(gW1 + (size_t)ds * HH);
        const ulonglong2* w1b = (const ulonglong2*)(gW1 + (size_t)(ds + 1) * HH);

        u64 p00 = 0ull, p01 = 0ull;   // step ds   dots (packed even/odd)
        u64 p10 = 0ull, p11 = 0ull;   // step ds+1 dots
#pragma unroll
        for (int k4 = 0; k4 < NP / 2; k4++) {
            const int f4 = wg + 256 * k4;
            ulonglong2 wA  = w1a[f4];               // LDG.128, L1-hot
            ulonglong2 wB  = w1b[f4];
            ulonglong2 w2a = sW2[f4];               // m=0, conflict-free LDS.128
            ulonglong2 w2b = sW2[SW2_U + f4];       // m=1
#pragma unroll
            for (int m = 0; m < 2; m++) {
                const int q = 2 * k4 + m;
                const ulonglong2 w2 = m ? w2b : w2a;
                u64 hA = hp[q];
                // 2 of 8 pairs on MUFU.TANH (saves 7 FMA at zero MUFU cost)
                u64 t0 = ((q & 3) == 0) ? tanh2_approx(hA) : tanh2_fma(hA);
                p00 = fma2(t0, w2.x, p00);
                p01 = fma2(t0, w2.y, p01);
                hA = fma2(x0p, m ? wA.y : wA.x, hA);
                u64 t1 = ((q & 3) == 0) ? tanh2_approx(hA) : tanh2_fma(hA);
                p10 = fma2(t1, w2.x, p10);
                p11 = fma2(t1, w2.y, p11);
                hp[q] = fma2(x1p, m ? wB.y : wB.x, hA);
            }
        }
        // fold even/odd halves, repack (col0,col1), packed 3-round butterfly
        float u, v;
        upk(u, v, p00); float a00 = u + v;
        upk(u, v, p01); float a01 = u + v;
        upk(u, v, p10); float a10 = u + v;
        upk(u, v, p11); float a11 = u + v;
        u64 c0 = pk(a00, a01);        // step ds:   (col0, col1)
        u64 c1 = pk(a10, a11);        // step ds+1: (col0, col1)
#pragma unroll
        for (int off = 16; off >= 4; off >>= 1) {
            c0 = add2(c0, __shfl_xor_sync(0xffffffffu, c0, off));
            c1 = add2(c1, __shfl_xor_sync(0xffffffffu, c1, off));
        }
        if (lane < 4) {
            *(u64*)&sPart[((ds    ) * SS + s) * NPW + wis * 4 + lane] = c0;
            *(u64*)&sPart[((ds + 1) * SS + s) * NPW + wis * 4 + lane] = c1;
        }
    }

    // deferred head: threads wg<64 each finish one step d, then product-reduce
    __syncthreads();
    const float b20 = gb2[0], b21 = gb2[1];
    if (wg < DD) {
        const int d = wg;
        float z0 = b20, z1 = b21;
#pragma unroll
        for (int w = 0; w < NPW; w++) {
            float2 v2 = sPart[(d * SS + s) * NPW + w];
            z0 += v2.x; z1 += v2.y;
        }
        float o0 = ftanh(z0), o1 = ftanh(z1);
        float nrm = fmaxf(sqrtf(o0 * o0 + o1 * o1), 1e-12f);
        float xd; { float dum; upk(xd, dum, sXp[s * DD + d]); }
        float sel = (xd > 0.0f ? o0 : o1) / nrm;
#pragma unroll
        for (int off = 16; off; off >>= 1)
            sel *= __shfl_xor_sync(0xffffffffu, sel, off);
        if (lane == 0) sProd[s * 2 + wis] = sel;   // wis = 0,1 only (wg<64)
    }
    __syncthreads();
    if (wg == 0) gout[n] = sProd[s * 2 + 0] * sProd[s * 2 + 1];
}

extern "C" void kernel_launch(void* const* d_in, const int* in_sizes, int n_in,
                              void* d_out, int out_size) {
    const float* x  = (const float*)d_in[0];
    const float* W1 = (const float*)d_in[1];
    const float* b1 = (const float*)d_in[2];
    const float* W2 = (const float*)d_in[3];
    const float* b2 = (const float*)d_in[4];
    cudaFuncSetAttribute(qnade_kernel,
                         cudaFuncAttributeMaxDynamicSharedMemorySize, SMEM_BYTES);
    qnade_kernel<<<NN / SS, BLOCK, SMEM_BYTES>>>(x, W1, b1, W2, b2, (float*)d_out);
}

// round 16
// speedup vs baseline: 1.4671x; 1.4671x over previous
#include <cuda_runtime.h>

#define NN    8192
#define DD    64
#define HH    4096
#define SS    2          // samples per block
#define NP    8          // hidden-unit pairs per thread (16 units)
#define BLOCK 512

typedef unsigned long long u64;

static __device__ __forceinline__ u64 pk(float lo, float hi) {
    u64 r; asm("mov.b64 %0,{%1,%2};" : "=l"(r) : "f"(lo), "f"(hi)); return r;
}
static __device__ __forceinline__ void upk(float& lo, float& hi, u64 v) {
    asm("mov.b64 {%0,%1},%2;" : "=f"(lo), "=f"(hi) : "l"(v));
}
static __device__ __forceinline__ u64 fma2(u64 a, u64 b, u64 c) {
    u64 d; asm("fma.rn.f32x2 %0,%1,%2,%3;" : "=l"(d) : "l"(a), "l"(b), "l"(c)); return d;
}
static __device__ __forceinline__ u64 mul2(u64 a, u64 b) {
    u64 d; asm("mul.rn.f32x2 %0,%1,%2;" : "=l"(d) : "l"(a), "l"(b)); return d;
}
static __device__ __forceinline__ u64 add2(u64 a, u64 b) {
    u64 d; asm("add.rn.f32x2 %0,%1,%2;" : "=l"(d) : "l"(a), "l"(b)); return d;
}
static __device__ __forceinline__ float frsq(float x) {
    float r; asm("rsqrt.approx.f32 %0,%1;" : "=f"(r) : "f"(x)); return r;
}
static __device__ __forceinline__ float ftanh(float x) {
    float e = __expf(2.0f * x);
    return 1.0f - __fdividef(2.0f, e + 1.0f);
}
// FMA-path packed tanh: t = s*rsqrt(1+s^2), s = h*P(h^2) (deg-3 sinh Taylor)
static __device__ __forceinline__ u64 tanh2_fma(u64 hA) {
    const u64 C3  = pk(1.98412698e-4f, 1.98412698e-4f);   // 1/7!
    const u64 C2  = pk(8.33333333e-3f, 8.33333333e-3f);   // 1/5!
    const u64 C1  = pk(1.66666667e-1f, 1.66666667e-1f);   // 1/3!
    const u64 ONE = pk(1.0f, 1.0f);
    u64 y = mul2(hA, hA);
    u64 p = fma2(C3, y, C2);
    p = fma2(p, y, C1);
    p = fma2(p, y, ONE);
    u64 sv = mul2(p, hA);
    u64 dd2 = fma2(sv, sv, ONE);
    float dl, dh; upk(dl, dh, dd2);
    return mul2(sv, pk(frsq(dl), frsq(dh)));
}

// smem: packed W2 + packed spins + partials + products (W1 in L1 via LDG)
#define SW2_U 1024                       // ulonglong2 entries per m-plane
#define NPW   32                         // partials per (step, sample)
#define SMEM_BYTES (2*SW2_U*16 + SS*DD*8 + DD*SS*NPW*8 + SS*2*4)

__global__ void __launch_bounds__(BLOCK, 2)
qnade_kernel(const float* __restrict__ gx,  const float* __restrict__ gW1,
             const float* __restrict__ gb1, const float* __restrict__ gW2,
             const float* __restrict__ gb2, float* __restrict__ gout)
{
    extern __shared__ char sm_[];
    ulonglong2* sW2   = (ulonglong2*)sm_;                   // [2][1024] (m-major)
    u64*        sXp   = (u64*)(sW2 + 2 * SW2_U);            // [SS][DD] packed spins
    float2*     sPart = (float2*)(sXp + SS * DD);           // [DD][SS][NPW]
    float*      sProd = (float*)(sPart + DD * SS * NPW);    // [SS][2]

    const int tid  = threadIdx.x;
    const int s    = tid >> 8;       // sample within block (0..1)
    const int wg   = tid & 255;      // thread within sample group
    const int wis  = wg >> 5;        // warp within sample group (0..7)
    const int lane = tid & 31;
    const int n    = blockIdx.x * SS + s;

    for (int i = tid; i < SS * DD; i += BLOCK) {
        float xv = gx[blockIdx.x * SS * DD + i];
        sXp[i] = pk(xv, xv);
    }

    // stage W2 pre-transposed: float4 p = 2*f4+m -> plane m, entry f4:
    // {pk(w0_even,w0_odd), pk(w1_even,w1_odd)} for unit pair 2p,2p+1
    {
        const float4* w2v = (const float4*)gW2;             // [H,2] -> 2048 float4
        for (int p = tid; p < 2 * SW2_U; p += BLOCK) {
            float4 w = w2v[p];
            ulonglong2 e;
            e.x = pk(w.x, w.z);
            e.y = pk(w.y, w.w);
            sW2[((p & 1) << 10) + (p >> 1)] = e;
        }
    }

    // persistent packed state: thread wg owns units 4*f4..4*f4+3, f4 = wg+256*k4
    u64 hp[NP];
    {
        const ulonglong2* b1v = (const ulonglong2*)gb1;
#pragma unroll
        for (int k4 = 0; k4 < NP / 2; k4++) {
            ulonglong2 b = b1v[wg + 256 * k4];
            hp[2*k4+0] = b.x; hp[2*k4+1] = b.y;
        }
    }
    __syncthreads();   // sW2 / sXp staged

    for (int ds = 0; ds < DD; ds += 2) {
        if (ds == DD / 2) __syncthreads();    // single mid-kernel drift bound
        const u64 x0p = sXp[s * DD + ds];
        const u64 x1p = sXp[s * DD + ds + 1];
        const ulonglong2* w1a = (const ulonglong2*)(gW1 + (size_t)ds * HH);
        const ulonglong2* w1b = (const ulonglong2*)(gW1 + (size_t)(ds + 1) * HH);

        u64 p00 = 0ull, p01 = 0ull;   // step ds   dots (packed even/odd)
        u64 p10 = 0ull, p11 = 0ull;   // step ds+1 dots
#pragma unroll
        for (int k4 = 0; k4 < NP / 2; k4++) {
            const int f4 = wg + 256 * k4;
            ulonglong2 wA  = w1a[f4];               // LDG.128, L1-hot
            ulonglong2 wB  = w1b[f4];
            ulonglong2 w2a = sW2[f4];               // m=0, conflict-free LDS.128
            ulonglong2 w2b = sW2[SW2_U + f4];       // m=1
#pragma unroll
            for (int m = 0; m < 2; m++) {
                const int q = 2 * k4 + m;
                const ulonglong2 w2 = m ? w2b : w2a;
                u64 hA = hp[q];
                u64 t0 = tanh2_fma(hA);
                p00 = fma2(t0, w2.x, p00);
                p01 = fma2(t0, w2.y, p01);
                hA = fma2(x0p, m ? wA.y : wA.x, hA);
                u64 t1 = tanh2_fma(hA);
                p10 = fma2(t1, w2.x, p10);
                p11 = fma2(t1, w2.y, p11);
                hp[q] = fma2(x1p, m ? wB.y : wB.x, hA);
            }
        }
        // fold even/odd halves, repack (col0,col1), packed 3-round butterfly
        float u, v;
        upk(u, v, p00); float a00 = u + v;
        upk(u, v, p01); float a01 = u + v;
        upk(u, v, p10); float a10 = u + v;
        upk(u, v, p11); float a11 = u + v;
        u64 c0 = pk(a00, a01);        // step ds:   (col0, col1)
        u64 c1 = pk(a10, a11);        // step ds+1: (col0, col1)
#pragma unroll
        for (int off = 16; off >= 4; off >>= 1) {
            c0 = add2(c0, __shfl_xor_sync(0xffffffffu, c0, off));
            c1 = add2(c1, __shfl_xor_sync(0xffffffffu, c1, off));
        }
        if (lane < 4) {
            *(u64*)&sPart[((ds    ) * SS + s) * NPW + wis * 4 + lane] = c0;
            *(u64*)&sPart[((ds + 1) * SS + s) * NPW + wis * 4 + lane] = c1;
        }
    }

    // deferred head: threads wg<64 each finish one step d, then product-reduce
    __syncthreads();
    const float b20 = gb2[0], b21 = gb2[1];
    if (wg < DD) {
        const int d = wg;
        float z0 = b20, z1 = b21;
#pragma unroll
        for (int w = 0; w < NPW; w++) {
            float2 v2 = sPart[(d * SS + s) * NPW + w];
            z0 += v2.x; z1 += v2.y;
        }
        float o0 = ftanh(z0), o1 = ftanh(z1);
        float nrm = fmaxf(sqrtf(o0 * o0 + o1 * o1), 1e-12f);
        float xd; { float dum; upk(xd, dum, sXp[s * DD + d]); }
        float sel = (xd > 0.0f ? o0 : o1) / nrm;
#pragma unroll
        for (int off = 16; off; off >>= 1)
            sel *= __shfl_xor_sync(0xffffffffu, sel, off);
        if (lane == 0) sProd[s * 2 + wis] = sel;   // wis = 0,1 only (wg<64)
    }
    __syncthreads();
    if (wg == 0) gout[n] = sProd[s * 2 + 0] * sProd[s * 2 + 1];
}

extern "C" void kernel_launch(void* const* d_in, const int* in_sizes, int n_in,
                              void* d_out, int out_size) {
    const float* x  = (const float*)d_in[0];
    const float* W1 = (const float*)d_in[1];
    const float* b1 = (const float*)d_in[2];
    const float* W2 = (const float*)d_in[3];
    const float* b2 = (const float*)d_in[4];
    cudaFuncSetAttribute(qnade_kernel,
                         cudaFuncAttributeMaxDynamicSharedMemorySize, SMEM_BYTES);
    qnade_kernel<<<NN / SS, BLOCK, SMEM_BYTES>>>(x, W1, b1, W2, b2, (float*)d_out);
}

// round 17
// speedup vs baseline: 1.5696x; 1.0698x over previous
#include <cuda_runtime.h>

#define NN    8192
#define DD    64
#define HH    4096
#define SS    2          // samples per block
#define NP    8          // hidden-unit pairs per thread (16 units)
#define BLOCK 512

typedef unsigned long long u64;

static __device__ __forceinline__ u64 pk(float lo, float hi) {
    u64 r; asm("mov.b64 %0,{%1,%2};" : "=l"(r) : "f"(lo), "f"(hi)); return r;
}
static __device__ __forceinline__ void upk(float& lo, float& hi, u64 v) {
    asm("mov.b64 {%0,%1},%2;" : "=f"(lo), "=f"(hi) : "l"(v));
}
static __device__ __forceinline__ u64 fma2(u64 a, u64 b, u64 c) {
    u64 d; asm("fma.rn.f32x2 %0,%1,%2,%3;" : "=l"(d) : "l"(a), "l"(b), "l"(c)); return d;
}
static __device__ __forceinline__ u64 mul2(u64 a, u64 b) {
    u64 d; asm("mul.rn.f32x2 %0,%1,%2;" : "=l"(d) : "l"(a), "l"(b)); return d;
}
static __device__ __forceinline__ u64 add2(u64 a, u64 b) {
    u64 d; asm("add.rn.f32x2 %0,%1,%2;" : "=l"(d) : "l"(a), "l"(b)); return d;
}
static __device__ __forceinline__ float frsq(float x) {
    float r; asm("rsqrt.approx.f32 %0,%1;" : "=f"(r) : "f"(x)); return r;
}
static __device__ __forceinline__ float ftanh(float x) {
    float e = __expf(2.0f * x);
    return 1.0f - __fdividef(2.0f, e + 1.0f);
}
// FMA-path packed tanh: t = s*rsqrt(1+s^2), s = h*P(h^2) (deg-2 sinh Taylor)
// P(y) = 1 + y/6 + y^2/120 ; self-saturating error suppression in the tails.
static __device__ __forceinline__ u64 tanh2_fma(u64 hA) {
    const u64 C2  = pk(8.33333333e-3f, 8.33333333e-3f);   // 1/5!
    const u64 C1  = pk(1.66666667e-1f, 1.66666667e-1f);   // 1/3!
    const u64 ONE = pk(1.0f, 1.0f);
    u64 y = mul2(hA, hA);
    u64 p = fma2(C2, y, C1);
    p = fma2(p, y, ONE);
    u64 sv = mul2(p, hA);
    u64 dd2 = fma2(sv, sv, ONE);
    float dl, dh; upk(dl, dh, dd2);
    return mul2(sv, pk(frsq(dl), frsq(dh)));
}

// smem: packed W2 + packed spins + partials + products (W1 in L1 via LDG)
#define SW2_U 1024                       // ulonglong2 entries per m-plane
#define NPW   32                         // partials per (step, sample)
#define SMEM_BYTES (2*SW2_U*16 + SS*DD*8 + DD*SS*NPW*8 + SS*2*4)

__global__ void __launch_bounds__(BLOCK, 2)
qnade_kernel(const float* __restrict__ gx,  const float* __restrict__ gW1,
             const float* __restrict__ gb1, const float* __restrict__ gW2,
             const float* __restrict__ gb2, float* __restrict__ gout)
{
    extern __shared__ char sm_[];
    ulonglong2* sW2   = (ulonglong2*)sm_;                   // [2][1024] (m-major)
    u64*        sXp   = (u64*)(sW2 + 2 * SW2_U);            // [SS][DD] packed spins
    float2*     sPart = (float2*)(sXp + SS * DD);           // [DD][SS][NPW]
    float*      sProd = (float*)(sPart + DD * SS * NPW);    // [SS][2]

    const int tid  = threadIdx.x;
    const int s    = tid >> 8;       // sample within block (0..1)
    const int wg   = tid & 255;      // thread within sample group
    const int wis  = wg >> 5;        // warp within sample group (0..7)
    const int lane = tid & 31;
    const int n    = blockIdx.x * SS + s;

    for (int i = tid; i < SS * DD; i += BLOCK) {
        float xv = gx[blockIdx.x * SS * DD + i];
        sXp[i] = pk(xv, xv);
    }

    // stage W2 pre-transposed: float4 p = 2*f4+m -> plane m, entry f4:
    // {pk(w0_even,w0_odd), pk(w1_even,w1_odd)} for unit pair 2p,2p+1
    {
        const float4* w2v = (const float4*)gW2;             // [H,2] -> 2048 float4
        for (int p = tid; p < 2 * SW2_U; p += BLOCK) {
            float4 w = w2v[p];
            ulonglong2 e;
            e.x = pk(w.x, w.z);
            e.y = pk(w.y, w.w);
            sW2[((p & 1) << 10) + (p >> 1)] = e;
        }
    }

    // persistent packed state: thread wg owns units 4*f4..4*f4+3, f4 = wg+256*k4
    u64 hp[NP];
    {
        const ulonglong2* b1v = (const ulonglong2*)gb1;
#pragma unroll
        for (int k4 = 0; k4 < NP / 2; k4++) {
            ulonglong2 b = b1v[wg + 256 * k4];
            hp[2*k4+0] = b.x; hp[2*k4+1] = b.y;
        }
    }
    __syncthreads();   // sW2 / sXp staged

    for (int ds = 0; ds < DD; ds += 2) {
        if (ds == DD / 2) __syncthreads();    // single mid-kernel drift bound
        const u64 x0p = sXp[s * DD + ds];
        const u64 x1p = sXp[s * DD + ds + 1];
        const ulonglong2* w1a = (const ulonglong2*)(gW1 + (size_t)ds * HH);
        const ulonglong2* w1b = (const ulonglong2*)(gW1 + (size_t)(ds + 1) * HH);

        u64 p00 = 0ull, p01 = 0ull;   // step ds   dots (packed even/odd)
        u64 p10 = 0ull, p11 = 0ull;   // step ds+1 dots
#pragma unroll
        for (int k4 = 0; k4 < NP / 2; k4++) {
            const int f4 = wg + 256 * k4;
            ulonglong2 wA  = w1a[f4];               // LDG.128, L1-hot
            ulonglong2 wB  = w1b[f4];
            ulonglong2 w2a = sW2[f4];               // m=0, conflict-free LDS.128
            ulonglong2 w2b = sW2[SW2_U + f4];       // m=1
#pragma unroll
            for (int m = 0; m < 2; m++) {
                const int q = 2 * k4 + m;
                const ulonglong2 w2 = m ? w2b : w2a;
                u64 hA = hp[q];
                u64 t0 = tanh2_fma(hA);
                p00 = fma2(t0, w2.x, p00);
                p01 = fma2(t0, w2.y, p01);
                hA = fma2(x0p, m ? wA.y : wA.x, hA);
                u64 t1 = tanh2_fma(hA);
                p10 = fma2(t1, w2.x, p10);
                p11 = fma2(t1, w2.y, p11);
                hp[q] = fma2(x1p, m ? wB.y : wB.x, hA);
            }
        }
        // fold even/odd halves, repack (col0,col1), packed 3-round butterfly
        float u, v;
        upk(u, v, p00); float a00 = u + v;
        upk(u, v, p01); float a01 = u + v;
        upk(u, v, p10); float a10 = u + v;
        upk(u, v, p11); float a11 = u + v;
        u64 c0 = pk(a00, a01);        // step ds:   (col0, col1)
        u64 c1 = pk(a10, a11);        // step ds+1: (col0, col1)
#pragma unroll
        for (int off = 16; off >= 4; off >>= 1) {
            c0 = add2(c0, __shfl_xor_sync(0xffffffffu, c0, off));
            c1 = add2(c1, __shfl_xor_sync(0xffffffffu, c1, off));
        }
        if (lane < 4) {
            *(u64*)&sPart[((ds    ) * SS + s) * NPW + wis * 4 + lane] = c0;
            *(u64*)&sPart[((ds + 1) * SS + s) * NPW + wis * 4 + lane] = c1;
        }
    }

    // deferred head: threads wg<64 each finish one step d, then product-reduce
    __syncthreads();
    const float b20 = gb2[0], b21 = gb2[1];
    if (wg < DD) {
        const int d = wg;
        float z0 = b20, z1 = b21;
#pragma unroll
        for (int w = 0; w < NPW; w++) {
            float2 v2 = sPart[(d * SS + s) * NPW + w];
            z0 += v2.x; z1 += v2.y;
        }
        float o0 = ftanh(z0), o1 = ftanh(z1);
        float nrm = fmaxf(sqrtf(o0 * o0 + o1 * o1), 1e-12f);
        float xd; { float dum; upk(xd, dum, sXp[s * DD + d]); }
        float sel = (xd > 0.0f ? o0 : o1) / nrm;
#pragma unroll
        for (int off = 16; off; off >>= 1)
            sel *= __shfl_xor_sync(0xffffffffu, sel, off);
        if (lane == 0) sProd[s * 2 + wis] = sel;   // wis = 0,1 only (wg<64)
    }
    __syncthreads();
    if (wg == 0) gout[n] = sProd[s * 2 + 0] * sProd[s * 2 + 1];
}

extern "C" void kernel_launch(void* const* d_in, const int* in_sizes, int n_in,
                              void* d_out, int out_size) {
    const float* x  = (const float*)d_in[0];
    const float* W1 = (const float*)d_in[1];
    const float* b1 = (const float*)d_in[2];
    const float* W2 = (const float*)d_in[3];
    const float* b2 = (const float*)d_in[4];
    cudaFuncSetAttribute(qnade_kernel,
                         cudaFuncAttributeMaxDynamicSharedMemorySize, SMEM_BYTES);
    qnade_kernel<<<NN / SS, BLOCK, SMEM_BYTES>>>(x, W1, b1, W2, b2, (float*)d_out);
}